// round 10
// baseline (speedup 1.0000x reference)
#include <cuda_runtime.h>
#include <cuda_bf16.h>
#include <math.h>
#include <stdint.h>

#define Bn 512
#define Vn 128
#define Dn 256
#define Hn 4
#define DHn 64

// ---------------- scratch (no cudaMalloc allowed) ----------------
__device__ __nv_bfloat16 g_Wh[Dn * Dn];  // W hi
__device__ __nv_bfloat16 g_Wl[Dn * Dn];  // W lo
__device__ float g_efm[Hn * Vn * Vn];    // TRANSPOSED: [h][j][i] = adj? ef : -1e30
__device__ float g_efmax[Hn * Vn];       // [h][j] = max_i efm
__device__ int   g_mask_mode;            // 0=u8, 1=i32, 2=f32

#define NEGBIG (-1e30f)

// ---------------- helpers ----------------
__device__ __forceinline__ void mma_bf16(float* c, const uint32_t* a, uint32_t b0, uint32_t b1) {
    asm volatile(
        "mma.sync.aligned.m16n8k16.row.col.f32.bf16.bf16.f32 "
        "{%0,%1,%2,%3},{%4,%5,%6,%7},{%8,%9},{%0,%1,%2,%3};"
        : "+f"(c[0]), "+f"(c[1]), "+f"(c[2]), "+f"(c[3])
        : "r"(a[0]), "r"(a[1]), "r"(a[2]), "r"(a[3]), "r"(b0), "r"(b1));
}

__device__ __forceinline__ void ldsm_x4(uint32_t& r0, uint32_t& r1, uint32_t& r2, uint32_t& r3,
                                        uint32_t addr) {
    asm volatile("ldmatrix.sync.aligned.m8n8.x4.shared.b16 {%0,%1,%2,%3}, [%4];"
                 : "=r"(r0), "=r"(r1), "=r"(r2), "=r"(r3) : "r"(addr));
}
__device__ __forceinline__ void ldsm_x4_t(uint32_t& r0, uint32_t& r1, uint32_t& r2, uint32_t& r3,
                                          uint32_t addr) {
    asm volatile("ldmatrix.sync.aligned.m8n8.x4.trans.shared.b16 {%0,%1,%2,%3}, [%4];"
                 : "=r"(r0), "=r"(r1), "=r"(r2), "=r"(r3) : "r"(addr));
}
__device__ __forceinline__ uint32_t sptr(const void* p) {
    return (uint32_t)__cvta_generic_to_shared(p);
}

__device__ __forceinline__ void split2(float a, float b, uint32_t& hi, uint32_t& lo) {
    __nv_bfloat16 ha = __float2bfloat16_rn(a);
    __nv_bfloat16 hb = __float2bfloat16_rn(b);
    float ra = a - __bfloat162float(ha);
    float rb = b - __bfloat162float(hb);
    __nv_bfloat162 vh; vh.x = ha; vh.y = hb;
    __nv_bfloat162 vl; vl.x = __float2bfloat16_rn(ra); vl.y = __float2bfloat16_rn(rb);
    hi = *reinterpret_cast<uint32_t*>(&vh);
    lo = *reinterpret_cast<uint32_t*>(&vl);
}

__device__ __forceinline__ float lrelu(float s) { return (s >= 0.f) ? s : 0.2f * s; }

// ---------------- mask dtype detection ----------------
__global__ void detect_mask_kernel(const unsigned int* __restrict__ m) {
    __shared__ int okInt, okFloat;
    if (threadIdx.x == 0) { okInt = 1; okFloat = 1; }
    __syncthreads();
    int badI = 0, badF = 0;
    for (int idx = threadIdx.x; idx < 16384; idx += 256) {
        unsigned int v = m[idx];
        if (v > 1u) badI = 1;
        if (v != 0u && v != 0x3f800000u) badF = 1;
    }
    if (badI) okInt = 0;
    if (badF) okFloat = 0;
    __syncthreads();
    if (threadIdx.x == 0) g_mask_mode = okFloat ? 2 : (okInt ? 1 : 0);
}

// ---------------- W convert ----------------
__global__ __launch_bounds__(256) void convert_w_kernel(const float* __restrict__ W) {
    int gid = blockIdx.x * 256 + threadIdx.x;
    float4 v = ((const float4*)W)[gid];
    uint32_t h01, l01, h23, l23;
    split2(v.x, v.y, h01, l01);
    split2(v.z, v.w, h23, l23);
    ((uint2*)g_Wh)[gid] = make_uint2(h01, h23);
    ((uint2*)g_Wl)[gid] = make_uint2(l01, l23);
}

// ---------------- efm[h][j][i] (transposed) ----------------
__global__ void ef_kernel(const float* __restrict__ ea, const float* __restrict__ Ew,
                          const int* __restrict__ adj) {
    int idx = blockIdx.x * blockDim.x + threadIdx.x;  // i*128+j
    if (idx >= Vn * Vn) return;
    float e0 = ea[idx * 2], e1 = ea[idx * 2 + 1];
    bool ok = adj[idx] != 0;
    int i = idx >> 7, j = idx & 127;
    int tidx = j * Vn + i;
    g_efm[0 * 16384 + tidx] = ok ? (e0 * Ew[0] + e1 * Ew[1]) : NEGBIG;
    g_efm[1 * 16384 + tidx] = ok ? (e0 * Ew[2] + e1 * Ew[3]) : NEGBIG;
    g_efm[2 * 16384 + tidx] = ok ? (e0 * Ew[4] + e1 * Ew[5]) : NEGBIG;
    g_efm[3 * 16384 + tidx] = ok ? (e0 * Ew[6] + e1 * Ew[7]) : NEGBIG;
}

// ---------------- efmax[h][j] = max_i efm[h][j][i] ----------------
__global__ void efmax_kernel() {
    int h = blockIdx.x, j = threadIdx.x;
    const float4* row = (const float4*)(g_efm + h * 16384 + j * Vn);
    float m = -4e30f;
#pragma unroll 8
    for (int q = 0; q < 32; q++) {
        float4 v = row[q];
        m = fmaxf(m, fmaxf(fmaxf(v.x, v.y), fmaxf(v.z, v.w)));
    }
    g_efmax[h * Vn + j] = m;
}

// ================= fused per-batch kernel =================
// SMEM layout (bytes):
//   sWxh  [128][264] bf16 @ 0        67584   Wx hi, row stride RSTR=264 (132 w == 4 mod 32)
//   sWxl  @ 67584                    67584   Wx lo
//   sAh   @ 135168                   10240   x-tile hi, 128 x 40 bf16
//   sAl   @ 145408                   10240
//   sBh   @ 155648                   20480   W-tile hi, 256 x 40 bf16
//   sBl   @ 176128                   20480
//   misc  @ 196608                   ~5.2KB  (overlaps nothing)
#define RSTR 264
#define OFF_WXL 67584
#define OFF_AH 135168
#define OFF_AL 145408
#define OFF_BH 155648
#define OFF_BL 176128
#define OFF_MISC 196608
#define FUSED_SMEM 201984
static_assert(FUSED_SMEM <= 227328, "smem too big");

__global__ __launch_bounds__(512) void fused_kernel(const float* __restrict__ x,
                                                    const void* __restrict__ maskp,
                                                    const float* __restrict__ a,
                                                    float* __restrict__ out) {
    extern __shared__ char smem[];
    float* sAvec = (float*)(smem + OFF_MISC);  // 128
    float* sMb   = sAvec + 128;                // 128
    float* sSrc  = sAvec + 256;                // 512 = [h][i]
    float* sDst  = sAvec + 768;                // 512
    float* sMax  = sAvec + 1280;               // 4

    int b = blockIdx.x;
    int t = threadIdx.x;
    int w = t >> 5, lane = t & 31;

    // a-vec + mask bias (used much later; plenty of syncs in between)
    if (t < 128) {
        sAvec[t] = a[t];
        int mode = g_mask_mode;
        bool mv;
        int idx = b * Vn + t;
        if (mode == 0)      mv = ((const unsigned char*)maskp)[idx] != 0;
        else if (mode == 1) mv = ((const int*)maskp)[idx] != 0;
        else                mv = ((const float*)maskp)[idx] != 0.f;
        sMb[t] = mv ? NEGBIG : 0.f;
    }

    // ---------------- phase 1: Wx[b] = x[b] @ W^T into SMEM ----------------
    {
        const float* xb = x + (size_t)b * Vn * Dn;
        int wm = w & 3, wn = w >> 2;  // warp tile 32m x 64n

        int rowoffA = ((lane >> 3) & 1) * 8 + (lane & 7);
        int coloffA = (lane >> 4) * 8;
        int rowoffB = (lane >> 4) * 8 + (lane & 7);
        int coloffB = ((lane >> 3) & 1) * 8;

        const uint4* gwh4 = (const uint4*)g_Wh;
        const uint4* gwl4 = (const uint4*)g_Wl;

        int arow0 = t >> 3, acq0 = t & 7;
        int arow1 = arow0 + 64;
        int brow0 = t >> 1, bhalf = t & 1;

        float4 ax0, ax1;
        uint4 rbh0, rbh1, rbl0, rbl1;

        float acc[2][8][4];
#pragma unroll
        for (int mt = 0; mt < 2; mt++)
#pragma unroll
            for (int nt = 0; nt < 8; nt++)
#pragma unroll
                for (int r = 0; r < 4; r++) acc[mt][nt][r] = 0.f;

#define F_LDG(k0)                                                                  \
    do {                                                                           \
        ax0 = *(const float4*)(xb + (size_t)arow0 * Dn + (k0) + acq0 * 4);         \
        ax1 = *(const float4*)(xb + (size_t)arow1 * Dn + (k0) + acq0 * 4);         \
        int bi0 = (brow0 * (Dn / 2) + ((k0) >> 1) + bhalf * 8) >> 2;               \
        rbh0 = gwh4[bi0]; rbh1 = gwh4[bi0 + 1];                                    \
        rbl0 = gwl4[bi0]; rbl1 = gwl4[bi0 + 1];                                    \
    } while (0)

#define F_STS()                                                                    \
    do {                                                                           \
        uint32_t* ah = (uint32_t*)(smem + OFF_AH);                                 \
        uint32_t* al = (uint32_t*)(smem + OFF_AL);                                 \
        uint4* bh = (uint4*)(smem + OFF_BH);                                       \
        uint4* bl = (uint4*)(smem + OFF_BL);                                       \
        uint32_t h01, l01, h23, l23;                                               \
        split2(ax0.x, ax0.y, h01, l01); split2(ax0.z, ax0.w, h23, l23);            \
        ah[arow0 * 20 + acq0 * 2] = h01; ah[arow0 * 20 + acq0 * 2 + 1] = h23;      \
        al[arow0 * 20 + acq0 * 2] = l01; al[arow0 * 20 + acq0 * 2 + 1] = l23;      \
        split2(ax1.x, ax1.y, h01, l01); split2(ax1.z, ax1.w, h23, l23);            \
        ah[arow1 * 20 + acq0 * 2] = h01; ah[arow1 * 20 + acq0 * 2 + 1] = h23;      \
        al[arow1 * 20 + acq0 * 2] = l01; al[arow1 * 20 + acq0 * 2 + 1] = l23;      \
        bh[brow0 * 5 + bhalf * 2] = rbh0; bh[brow0 * 5 + bhalf * 2 + 1] = rbh1;    \
        bl[brow0 * 5 + bhalf * 2] = rbl0; bl[brow0 * 5 + bhalf * 2 + 1] = rbl1;    \
    } while (0)

        F_LDG(0);
        uint32_t aAh = sptr(smem + OFF_AH), aAl = sptr(smem + OFF_AL);
        uint32_t aBh = sptr(smem + OFF_BH), aBl = sptr(smem + OFF_BL);

        for (int ki = 0; ki < 8; ki++) {
            F_STS();
            __syncthreads();
            if (ki < 7) F_LDG((ki + 1) * 32);
#pragma unroll
            for (int ks = 0; ks < 32; ks += 16) {
                uint32_t Ah[2][4], Al[2][4];
#pragma unroll
                for (int mt = 0; mt < 2; mt++) {
                    uint32_t off = (wm * 32 + mt * 16 + rowoffA) * 80 + (ks + coloffA) * 2;
                    ldsm_x4(Ah[mt][0], Ah[mt][1], Ah[mt][2], Ah[mt][3], aAh + off);
                    ldsm_x4(Al[mt][0], Al[mt][1], Al[mt][2], Al[mt][3], aAl + off);
                }
#pragma unroll
                for (int nb = 0; nb < 4; nb++) {
                    uint32_t off = (wn * 64 + nb * 16 + rowoffB) * 80 + (ks + coloffB) * 2;
                    uint32_t bh0, bh1, bh2, bh3, bl0, bl1, bl2, bl3;
                    ldsm_x4(bh0, bh1, bh2, bh3, aBh + off);
                    ldsm_x4(bl0, bl1, bl2, bl3, aBl + off);
#pragma unroll
                    for (int mt = 0; mt < 2; mt++) {
                        mma_bf16(acc[mt][nb * 2], Ah[mt], bh0, bh1);
                        mma_bf16(acc[mt][nb * 2], Al[mt], bh0, bh1);
                        mma_bf16(acc[mt][nb * 2], Ah[mt], bl0, bl1);
                        mma_bf16(acc[mt][nb * 2 + 1], Ah[mt], bh2, bh3);
                        mma_bf16(acc[mt][nb * 2 + 1], Al[mt], bh2, bh3);
                        mma_bf16(acc[mt][nb * 2 + 1], Ah[mt], bl2, bl3);
                    }
                }
            }
            __syncthreads();
        }

        // epilogue: acc -> sWx hi/lo (row stride RSTR)
        uint32_t* wxh = (uint32_t*)smem;
        uint32_t* wxl = (uint32_t*)(smem + OFF_WXL);
#pragma unroll
        for (int mt = 0; mt < 2; mt++)
#pragma unroll
            for (int nt = 0; nt < 8; nt++) {
                int row0 = wm * 32 + mt * 16 + (lane >> 2);
                int col = wn * 64 + nt * 8 + (lane & 3) * 2;
                uint32_t hi, lo;
                split2(acc[mt][nt][0], acc[mt][nt][1], hi, lo);
                wxh[row0 * (RSTR / 2) + (col >> 1)] = hi;
                wxl[row0 * (RSTR / 2) + (col >> 1)] = lo;
                split2(acc[mt][nt][2], acc[mt][nt][3], hi, lo);
                wxh[(row0 + 8) * (RSTR / 2) + (col >> 1)] = hi;
                wxl[(row0 + 8) * (RSTR / 2) + (col >> 1)] = lo;
            }
    }
    __syncthreads();

    // ---------------- interphase: s_src/s_dst for all 4 heads ----------------
    {
        int i = t & 127, hsel = t >> 7;  // (i, head)
        const uint32_t* wxh = (const uint32_t*)smem + i * (RSTR / 2) + hsel * 32;
        const uint32_t* wxl = (const uint32_t*)(smem + OFF_WXL) + i * (RSTR / 2) + hsel * 32;
        const float* av = sAvec + hsel * 64;
        float ss = 0.f, sd = 0.f;
#pragma unroll
        for (int q2 = 0; q2 < 32; q2++) {
            uint32_t uh = wxh[q2], ul = wxl[q2];
            float2 fh = __bfloat1622float2(*(__nv_bfloat162*)&uh);
            float2 fl = __bfloat1622float2(*(__nv_bfloat162*)&ul);
            float f0 = fh.x + fl.x, f1 = fh.y + fl.y;
            int d = q2 * 2;
            ss += f0 * av[d] + f1 * av[d + 1];
            sd += f0 * sAvec[64 + hsel * 64 + d] + f1 * sAvec[64 + hsel * 64 + d + 1];
        }
        // NOTE: a layout is a[0:64]=src, a[64:128]=dst per-head-shared (a is 2*Dh)
        // recompute: src uses sAvec[d'], dst uses sAvec[64+d'] with d' = local dim
        // fix: redo with local dim
        ss = 0.f; sd = 0.f;
#pragma unroll
        for (int q2 = 0; q2 < 32; q2++) {
            uint32_t uh = wxh[q2], ul = wxl[q2];
            float2 fh = __bfloat1622float2(*(__nv_bfloat162*)&uh);
            float2 fl = __bfloat1622float2(*(__nv_bfloat162*)&ul);
            float f0 = fh.x + fl.x, f1 = fh.y + fl.y;
            int d = q2 * 2;  // local dim within head
            ss += f0 * sAvec[d] + f1 * sAvec[d + 1];
            sd += f0 * sAvec[64 + d] + f1 * sAvec[64 + d + 1];
        }
        sSrc[hsel * 128 + i] = ss + sMb[i];
        sDst[hsel * 128 + i] = sd + sMb[i];
    }
    __syncthreads();
    if (w < 4 && lane < 32) {
        const float* s = sSrc + w * 128;
        float m = fmaxf(fmaxf(s[lane], s[lane + 32]), fmaxf(s[lane + 64], s[lane + 96]));
        m = fmaxf(m, __shfl_xor_sync(0xffffffffu, m, 1));
        m = fmaxf(m, __shfl_xor_sync(0xffffffffu, m, 2));
        m = fmaxf(m, __shfl_xor_sync(0xffffffffu, m, 4));
        m = fmaxf(m, __shfl_xor_sync(0xffffffffu, m, 8));
        m = fmaxf(m, __shfl_xor_sync(0xffffffffu, m, 16));
        if (lane == 0) sMax[w] = m;
    }
    __syncthreads();

    // ---------------- phase 2: attention, 8 warps per head, 2 heads/group ----------------
    int hgrp = w >> 3;      // 0 or 1
    int wa = w & 7;         // warp within group
    int q = lane >> 2, cpos = (lane & 3) * 2;
    int j0 = wa * 16 + q;
    int j1 = j0 + 8;

    int rowoffBt = ((lane >> 3) & 1) * 8 + (lane & 7);
    int coloffBt = (lane >> 4) * 8;
    uint32_t aWh = sptr(smem), aWl = sptr(smem + OFF_WXL);

    for (int hc = 0; hc < 2; hc++) {
        int h = hgrp * 2 + hc;
        const float* efT = g_efm + h * (Vn * Vn);
        const float* sSrcH = sSrc + h * 128;
        float dst0 = sDst[h * 128 + j0], dst1 = sDst[h * 128 + j1];
        float maxSrcV = sMax[h];
        float m0v = lrelu(maxSrcV + dst0 + g_efmax[h * Vn + j0]);
        float m1v = lrelu(maxSrcV + dst1 + g_efmax[h * Vn + j1]);

        float acc[8][4];
#pragma unroll
        for (int nt = 0; nt < 8; nt++)
#pragma unroll
            for (int r = 0; r < 4; r++) acc[nt][r] = 0.f;

        float s0 = 0.f, s1 = 0.f;
#pragma unroll
        for (int k0 = 0; k0 < 8; k0++) {
            int ib = k0 * 16 + cpos;
            float2 sA = *(const float2*)&sSrcH[ib];
            float2 sB = *(const float2*)&sSrcH[ib + 8];
            float2 eA0 = *(const float2*)&efT[j0 * Vn + ib];
            float2 eB0 = *(const float2*)&efT[j0 * Vn + ib + 8];
            float2 eA1 = *(const float2*)&efT[j1 * Vn + ib];
            float2 eB1 = *(const float2*)&efT[j1 * Vn + ib + 8];
            float p00 = __expf(lrelu(sA.x + dst0 + eA0.x) - m0v);
            float p01 = __expf(lrelu(sA.y + dst0 + eA0.y) - m0v);
            float p02 = __expf(lrelu(sB.x + dst0 + eB0.x) - m0v);
            float p03 = __expf(lrelu(sB.y + dst0 + eB0.y) - m0v);
            float p10 = __expf(lrelu(sA.x + dst1 + eA1.x) - m1v);
            float p11 = __expf(lrelu(sA.y + dst1 + eA1.y) - m1v);
            float p12 = __expf(lrelu(sB.x + dst1 + eB1.x) - m1v);
            float p13 = __expf(lrelu(sB.y + dst1 + eB1.y) - m1v);
            s0 += p00 + p01 + p02 + p03;
            s1 += p10 + p11 + p12 + p13;
            uint32_t Ah[4], Al[4];
            split2(p00, p01, Ah[0], Al[0]);
            split2(p10, p11, Ah[1], Al[1]);
            split2(p02, p03, Ah[2], Al[2]);
            split2(p12, p13, Ah[3], Al[3]);
#pragma unroll
            for (int nc = 0; nc < 4; nc++) {
                uint32_t offB =
                    ((k0 * 16 + rowoffBt) * RSTR + h * DHn + nc * 16 + coloffBt) * 2;
                uint32_t bh0, bh1, bh2, bh3, bl0, bl1, bl2, bl3;
                ldsm_x4_t(bh0, bh1, bh2, bh3, aWh + offB);
                ldsm_x4_t(bl0, bl1, bl2, bl3, aWl + offB);
                mma_bf16(acc[nc * 2], Ah, bh0, bh1);
                mma_bf16(acc[nc * 2], Al, bh0, bh1);
                mma_bf16(acc[nc * 2], Ah, bl0, bl1);
                mma_bf16(acc[nc * 2 + 1], Ah, bh2, bh3);
                mma_bf16(acc[nc * 2 + 1], Al, bh2, bh3);
                mma_bf16(acc[nc * 2 + 1], Ah, bl2, bl3);
            }
        }
        s0 += __shfl_xor_sync(0xffffffffu, s0, 1);
        s0 += __shfl_xor_sync(0xffffffffu, s0, 2);
        s1 += __shfl_xor_sync(0xffffffffu, s1, 1);
        s1 += __shfl_xor_sync(0xffffffffu, s1, 2);
        float inv0 = 1.0f / s0;
        float inv1 = 1.0f / s1;

        bool msk0 = (sMb[j0] != 0.f);
        bool msk1 = (sMb[j1] != 0.f);
#pragma unroll
        for (int nt = 0; nt < 8; nt++) {
            int dd = nt * 8 + cpos;
            {
                float v0 = acc[nt][0] * inv0;
                float v1 = acc[nt][1] * inv0;
                float2 o;
                o.x = msk0 ? 0.f : (v0 > 0.f ? v0 : __expf(v0) - 1.f);
                o.y = msk0 ? 0.f : (v1 > 0.f ? v1 : __expf(v1) - 1.f);
                *(float2*)(out + (size_t)(b * Vn + j0) * Dn + h * DHn + dd) = o;
            }
            {
                float v0 = acc[nt][2] * inv1;
                float v1 = acc[nt][3] * inv1;
                float2 o;
                o.x = msk1 ? 0.f : (v0 > 0.f ? v0 : __expf(v0) - 1.f);
                o.y = msk1 ? 0.f : (v1 > 0.f ? v1 : __expf(v1) - 1.f);
                *(float2*)(out + (size_t)(b * Vn + j1) * Dn + h * DHn + dd) = o;
            }
        }
    }
}

// ---------------- launch ----------------
extern "C" void kernel_launch(void* const* d_in, const int* in_sizes, int n_in,
                              void* d_out, int out_size) {
    const float* x    = (const float*)d_in[0];
    const int*   adj  = (const int*)d_in[1];
    const float* ea   = (const float*)d_in[2];
    const void*  mask = (const void*)d_in[3];
    const float* W    = (const float*)d_in[4];
    const float* a    = (const float*)d_in[5];
    const float* Ew   = (const float*)d_in[6];
    float* out = (float*)d_out;

    cudaFuncSetAttribute(fused_kernel, cudaFuncAttributeMaxDynamicSharedMemorySize,
                         FUSED_SMEM);

    detect_mask_kernel<<<1, 256>>>((const unsigned int*)mask);
    ef_kernel<<<(Vn * Vn + 255) / 256, 256>>>(ea, Ew, adj);
    efmax_kernel<<<Hn, Vn>>>();
    convert_w_kernel<<<(Dn * Dn / 4) / 256, 256>>>(W);
    fused_kernel<<<Bn, 512, FUSED_SMEM>>>(x, mask, a, out);
}

// round 11
// speedup vs baseline: 1.3263x; 1.3263x over previous
#include <cuda_runtime.h>
#include <cuda_bf16.h>
#include <math.h>
#include <stdint.h>

#define Bn 512
#define Vn 128
#define Dn 256
#define Hn 4
#define DHn 64

// ---------------- scratch (no cudaMalloc allowed) ----------------
__device__ __nv_bfloat16 g_Wh[Dn * Dn];                // W hi
__device__ __nv_bfloat16 g_Wl[Dn * Dn];                // W lo
__device__ __nv_bfloat16 g_Wxh[(size_t)Bn * Vn * Dn];  // Wx hi
__device__ __nv_bfloat16 g_Wxl[(size_t)Bn * Vn * Dn];  // Wx lo
__device__ float g_efm[Hn * Vn * Vn];                  // TRANSPOSED: [h][j][i] = adj? ef : -1e30
__device__ unsigned int g_efgmax_u[Hn];                // encoded per-head global max (monotone u32)
__device__ int   g_mask_mode;                          // 0=u8, 1=i32, 2=f32

#define NEGBIG (-1e30f)

// ---------------- helpers ----------------
__device__ __forceinline__ void mma_bf16(float* c, const uint32_t* a, uint32_t b0, uint32_t b1) {
    asm volatile(
        "mma.sync.aligned.m16n8k16.row.col.f32.bf16.bf16.f32 "
        "{%0,%1,%2,%3},{%4,%5,%6,%7},{%8,%9},{%0,%1,%2,%3};"
        : "+f"(c[0]), "+f"(c[1]), "+f"(c[2]), "+f"(c[3])
        : "r"(a[0]), "r"(a[1]), "r"(a[2]), "r"(a[3]), "r"(b0), "r"(b1));
}

__device__ __forceinline__ void ldsm_x4(uint32_t& r0, uint32_t& r1, uint32_t& r2, uint32_t& r3,
                                        uint32_t addr) {
    asm volatile("ldmatrix.sync.aligned.m8n8.x4.shared.b16 {%0,%1,%2,%3}, [%4];"
                 : "=r"(r0), "=r"(r1), "=r"(r2), "=r"(r3) : "r"(addr));
}
__device__ __forceinline__ void ldsm_x4_t(uint32_t& r0, uint32_t& r1, uint32_t& r2, uint32_t& r3,
                                          uint32_t addr) {
    asm volatile("ldmatrix.sync.aligned.m8n8.x4.trans.shared.b16 {%0,%1,%2,%3}, [%4];"
                 : "=r"(r0), "=r"(r1), "=r"(r2), "=r"(r3) : "r"(addr));
}
__device__ __forceinline__ uint32_t sptr(const void* p) {
    return (uint32_t)__cvta_generic_to_shared(p);
}

__device__ __forceinline__ void split2(float a, float b, uint32_t& hi, uint32_t& lo) {
    __nv_bfloat16 ha = __float2bfloat16_rn(a);
    __nv_bfloat16 hb = __float2bfloat16_rn(b);
    float ra = a - __bfloat162float(ha);
    float rb = b - __bfloat162float(hb);
    __nv_bfloat162 vh; vh.x = ha; vh.y = hb;
    __nv_bfloat162 vl; vl.x = __float2bfloat16_rn(ra); vl.y = __float2bfloat16_rn(rb);
    hi = *reinterpret_cast<uint32_t*>(&vh);
    lo = *reinterpret_cast<uint32_t*>(&vl);
}

__device__ __forceinline__ float lrelu(float s) { return (s >= 0.f) ? s : 0.2f * s; }

// monotone float<->u32 encode for atomicMax over signed floats
__device__ __forceinline__ unsigned int encf(float f) {
    unsigned int u = __float_as_uint(f);
    return (u & 0x80000000u) ? ~u : (u | 0x80000000u);
}
__device__ __forceinline__ float decf(unsigned int u) {
    return (u & 0x80000000u) ? __uint_as_float(u & 0x7FFFFFFFu) : __uint_as_float(~u);
}

// ---------------- merged prep kernel ----------------
// blocks [0,64):   efm (transposed) + per-head global max via atomicMax
// blocks [64,128): convert W -> hi/lo bf16
// block  128:      mask dtype detection
__global__ __launch_bounds__(256) void prep_kernel(const float* __restrict__ ea,
                                                   const float* __restrict__ Ew,
                                                   const int* __restrict__ adj,
                                                   const float* __restrict__ W,
                                                   const unsigned int* __restrict__ maskw) {
    int blk = blockIdx.x;
    int t = threadIdx.x;
    if (blk < 64) {
        int idx = blk * 256 + t;  // i*128 + j
        float e0 = ea[idx * 2], e1 = ea[idx * 2 + 1];
        bool ok = adj[idx] != 0;
        int i = idx >> 7, j = idx & 127;
        int tidx = j * Vn + i;
        float v0 = ok ? (e0 * Ew[0] + e1 * Ew[1]) : NEGBIG;
        float v1 = ok ? (e0 * Ew[2] + e1 * Ew[3]) : NEGBIG;
        float v2 = ok ? (e0 * Ew[4] + e1 * Ew[5]) : NEGBIG;
        float v3 = ok ? (e0 * Ew[6] + e1 * Ew[7]) : NEGBIG;
        g_efm[0 * 16384 + tidx] = v0;
        g_efm[1 * 16384 + tidx] = v1;
        g_efm[2 * 16384 + tidx] = v2;
        g_efm[3 * 16384 + tidx] = v3;
        // warp-reduce max per head, then one atomic per warp per head
        float m[4] = {v0, v1, v2, v3};
#pragma unroll
        for (int h = 0; h < 4; h++) {
            float x = m[h];
            x = fmaxf(x, __shfl_xor_sync(0xffffffffu, x, 1));
            x = fmaxf(x, __shfl_xor_sync(0xffffffffu, x, 2));
            x = fmaxf(x, __shfl_xor_sync(0xffffffffu, x, 4));
            x = fmaxf(x, __shfl_xor_sync(0xffffffffu, x, 8));
            x = fmaxf(x, __shfl_xor_sync(0xffffffffu, x, 16));
            if ((t & 31) == 0) atomicMax(&g_efgmax_u[h], encf(x));
        }
    } else if (blk < 128) {
        int gid = (blk - 64) * 256 + t;  // 16384 float4
        float4 v = ((const float4*)W)[gid];
        uint32_t h01, l01, h23, l23;
        split2(v.x, v.y, h01, l01);
        split2(v.z, v.w, h23, l23);
        ((uint2*)g_Wh)[gid] = make_uint2(h01, h23);
        ((uint2*)g_Wl)[gid] = make_uint2(l01, l23);
    } else {
        __shared__ int okInt, okFloat;
        if (t == 0) { okInt = 1; okFloat = 1; }
        __syncthreads();
        int badI = 0, badF = 0;
        for (int idx = t; idx < 16384; idx += 256) {
            unsigned int v = maskw[idx];
            if (v > 1u) badI = 1;
            if (v != 0u && v != 0x3f800000u) badF = 1;
        }
        if (badI) okInt = 0;
        if (badF) okFloat = 0;
        __syncthreads();
        if (t == 0) g_mask_mode = okFloat ? 2 : (okInt ? 1 : 0);
    }
}

// ---------------- GEMM1: Wx = x @ W^T, BM=128 BN=256 BK=32, 512 thr ----------------
// SMEM stage: Ah 10240 | Al 10240 | Bh 20480 | Bl 20480 = 61440; x2 stages
#define GSTAGE 61440
#define GEMM_SMEM (2 * GSTAGE)

__global__ __launch_bounds__(512) void gemm_wx_kernel(const float* __restrict__ x) {
    extern __shared__ char gs[];
    int m0 = blockIdx.x * 128;
    int t = threadIdx.x;
    int w = t >> 5, lane = t & 31;
    int wm = w & 3, wn = w >> 2;  // warp tile: 32m x 64n

    int rowoffA = ((lane >> 3) & 1) * 8 + (lane & 7);
    int coloffA = (lane >> 4) * 8;
    int rowoffB = (lane >> 4) * 8 + (lane & 7);
    int coloffB = ((lane >> 3) & 1) * 8;

    const uint4* gwh4 = (const uint4*)g_Wh;
    const uint4* gwl4 = (const uint4*)g_Wl;

    int arow0 = t >> 3, acq0 = t & 7;
    int arow1 = arow0 + 64;
    int brow0 = t >> 1, bhalf = t & 1;  // 512 threads cover 256 B rows x 2 halves

    float4 ax0, ax1;
    uint4 rbh0, rbh1, rbl0, rbl1;

    float acc[2][8][4];
#pragma unroll
    for (int mt = 0; mt < 2; mt++)
#pragma unroll
        for (int nt = 0; nt < 8; nt++)
#pragma unroll
            for (int r = 0; r < 4; r++) acc[mt][nt][r] = 0.f;

#define G_LDG(k0)                                                                     \
    do {                                                                              \
        ax0 = *(const float4*)(x + (size_t)(m0 + arow0) * Dn + (k0) + acq0 * 4);      \
        ax1 = *(const float4*)(x + (size_t)(m0 + arow1) * Dn + (k0) + acq0 * 4);      \
        int bi0 = (brow0 * (Dn / 2) + ((k0) >> 1) + bhalf * 8) >> 2;                  \
        rbh0 = gwh4[bi0]; rbh1 = gwh4[bi0 + 1];                                       \
        rbl0 = gwl4[bi0]; rbl1 = gwl4[bi0 + 1];                                       \
    } while (0)

#define G_STS(s)                                                                      \
    do {                                                                              \
        char* st = gs + (s) * GSTAGE;                                                 \
        uint32_t* ah = (uint32_t*)st;                                                 \
        uint32_t* al = (uint32_t*)(st + 10240);                                       \
        uint4* bh = (uint4*)(st + 20480);                                             \
        uint4* bl = (uint4*)(st + 40960);                                             \
        uint32_t h01, l01, h23, l23;                                                  \
        split2(ax0.x, ax0.y, h01, l01); split2(ax0.z, ax0.w, h23, l23);               \
        ah[arow0 * 20 + acq0 * 2] = h01; ah[arow0 * 20 + acq0 * 2 + 1] = h23;         \
        al[arow0 * 20 + acq0 * 2] = l01; al[arow0 * 20 + acq0 * 2 + 1] = l23;         \
        split2(ax1.x, ax1.y, h01, l01); split2(ax1.z, ax1.w, h23, l23);               \
        ah[arow1 * 20 + acq0 * 2] = h01; ah[arow1 * 20 + acq0 * 2 + 1] = h23;         \
        al[arow1 * 20 + acq0 * 2] = l01; al[arow1 * 20 + acq0 * 2 + 1] = l23;         \
        bh[brow0 * 5 + bhalf * 2] = rbh0; bh[brow0 * 5 + bhalf * 2 + 1] = rbh1;       \
        bl[brow0 * 5 + bhalf * 2] = rbl0; bl[brow0 * 5 + bhalf * 2 + 1] = rbl1;       \
    } while (0)

    G_LDG(0);
    G_STS(0);
    G_LDG(32);
    __syncthreads();

    for (int ki = 0; ki < 8; ki++) {
        char* st = gs + (ki & 1) * GSTAGE;
        uint32_t aAh = sptr(st), aAl = sptr(st + 10240);
        uint32_t aBh = sptr(st + 20480), aBl = sptr(st + 40960);
#pragma unroll
        for (int ks = 0; ks < 32; ks += 16) {
            uint32_t Ah[2][4], Al[2][4];
#pragma unroll
            for (int mt = 0; mt < 2; mt++) {
                uint32_t off = (wm * 32 + mt * 16 + rowoffA) * 80 + (ks + coloffA) * 2;
                ldsm_x4(Ah[mt][0], Ah[mt][1], Ah[mt][2], Ah[mt][3], aAh + off);
                ldsm_x4(Al[mt][0], Al[mt][1], Al[mt][2], Al[mt][3], aAl + off);
            }
#pragma unroll
            for (int nb = 0; nb < 4; nb++) {
                uint32_t off = (wn * 64 + nb * 16 + rowoffB) * 80 + (ks + coloffB) * 2;
                uint32_t bh0, bh1, bh2, bh3, bl0, bl1, bl2, bl3;
                ldsm_x4(bh0, bh1, bh2, bh3, aBh + off);
                ldsm_x4(bl0, bl1, bl2, bl3, aBl + off);
#pragma unroll
                for (int mt = 0; mt < 2; mt++) {
                    mma_bf16(acc[mt][nb * 2], Ah[mt], bh0, bh1);
                    mma_bf16(acc[mt][nb * 2], Al[mt], bh0, bh1);
                    mma_bf16(acc[mt][nb * 2], Ah[mt], bl0, bl1);
                    mma_bf16(acc[mt][nb * 2 + 1], Ah[mt], bh2, bh3);
                    mma_bf16(acc[mt][nb * 2 + 1], Al[mt], bh2, bh3);
                    mma_bf16(acc[mt][nb * 2 + 1], Ah[mt], bl2, bl3);
                }
            }
        }
        __syncthreads();
        if (ki < 7) {
            G_STS((ki + 1) & 1);
            if (ki < 6) G_LDG((ki + 2) * 32);
            __syncthreads();
        }
    }

#pragma unroll
    for (int mt = 0; mt < 2; mt++)
#pragma unroll
        for (int nt = 0; nt < 8; nt++) {
            int row0 = m0 + wm * 32 + mt * 16 + (lane >> 2);
            int col = wn * 64 + nt * 8 + (lane & 3) * 2;
            uint32_t hi, lo;
            split2(acc[mt][nt][0], acc[mt][nt][1], hi, lo);
            *(uint32_t*)&g_Wxh[(size_t)row0 * Dn + col] = hi;
            *(uint32_t*)&g_Wxl[(size_t)row0 * Dn + col] = lo;
            split2(acc[mt][nt][2], acc[mt][nt][3], hi, lo);
            *(uint32_t*)&g_Wxh[(size_t)(row0 + 8) * Dn + col] = hi;
            *(uint32_t*)&g_Wxl[(size_t)(row0 + 8) * Dn + col] = lo;
        }
}

// ---------------- fused attention per (b, h) ----------------
#define WSTR 72  // bf16 stride -> conflict-free ldmatrix
// SMEM: sWh 18432 | sWl 18432 | misc
#define ATT_SMEM_BYTES 41088

__global__ __launch_bounds__(256, 3) void gat_attn_kernel(const void* __restrict__ maskp,
                                                          const float* __restrict__ a,
                                                          float* __restrict__ out) {
    extern __shared__ char smem[];
    __nv_bfloat16* sWh = (__nv_bfloat16*)smem;
    __nv_bfloat16* sWl = (__nv_bfloat16*)(smem + 18432);
    float* sAvec = (float*)(smem + 36864);  // 128
    float* sMb = sAvec + 128;               // 128
    float* sSrc = sAvec + 256;              // 128
    float* sDst = sAvec + 384;              // 128
    float* sPS = sAvec + 512;               // 256
    float* sPD = sAvec + 768;               // 256
    float* sMax = sAvec + 1024;             // 1

    int h = blockIdx.x;
    int b = blockIdx.y;
    int t = threadIdx.x;

    if (t < 128) {
        sAvec[t] = a[t];
        int mode = g_mask_mode;
        bool mv;
        int idx = b * Vn + t;
        if (mode == 0)      mv = ((const unsigned char*)maskp)[idx] != 0;
        else if (mode == 1) mv = ((const int*)maskp)[idx] != 0;
        else                mv = ((const float*)maskp)[idx] != 0.f;
        sMb[t] = mv ? NEGBIG : 0.f;
    }
    __syncthreads();

    // ---- load Wx[b,:,h,:] hi/lo into sW [i][d] + partial a-dots ----
    {
        int i = t >> 1, half = t & 1;
        size_t base32 = ((size_t)(b * Vn + i) * Dn + h * DHn) >> 1;
        const uint4* ph4 = (const uint4*)((const uint32_t*)g_Wxh + base32 + half * 16);
        const uint4* pl4 = (const uint4*)((const uint32_t*)g_Wxl + base32 + half * 16);
        uint4 h4[4], l4[4];
#pragma unroll
        for (int q = 0; q < 4; q++) { h4[q] = ph4[q]; l4[q] = pl4[q]; }
        uint32_t* wh32 = (uint32_t*)sWh;
        uint32_t* wl32 = (uint32_t*)sWl;
        const uint32_t* hh = (const uint32_t*)h4;
        const uint32_t* ll = (const uint32_t*)l4;
        float ss = 0.f, sd = 0.f;
#pragma unroll
        for (int q = 0; q < 16; q++) {
            uint32_t uh = hh[q], ul = ll[q];
            int d = half * 32 + q * 2;
            wh32[i * (WSTR / 2) + (d >> 1)] = uh;
            wl32[i * (WSTR / 2) + (d >> 1)] = ul;
            float2 fh = __bfloat1622float2(*(__nv_bfloat162*)&uh);
            float2 fl = __bfloat1622float2(*(__nv_bfloat162*)&ul);
            float f0 = fh.x + fl.x, f1 = fh.y + fl.y;
            ss += f0 * sAvec[d] + f1 * sAvec[d + 1];
            sd += f0 * sAvec[64 + d] + f1 * sAvec[64 + d + 1];
        }
        sPS[t] = ss;
        sPD[t] = sd;
    }
    __syncthreads();
    if (t < 128) {
        sSrc[t] = sPS[2 * t] + sPS[2 * t + 1] + sMb[t];
        sDst[t] = sPD[2 * t] + sPD[2 * t + 1] + sMb[t];
    }
    __syncthreads();
    if (t < 32) {
        float m = fmaxf(fmaxf(sSrc[t], sSrc[t + 32]), fmaxf(sSrc[t + 64], sSrc[t + 96]));
        m = fmaxf(m, __shfl_xor_sync(0xffffffffu, m, 1));
        m = fmaxf(m, __shfl_xor_sync(0xffffffffu, m, 2));
        m = fmaxf(m, __shfl_xor_sync(0xffffffffu, m, 4));
        m = fmaxf(m, __shfl_xor_sync(0xffffffffu, m, 8));
        m = fmaxf(m, __shfl_xor_sync(0xffffffffu, m, 16));
        if (t == 0) sMax[0] = m;
    }
    __syncthreads();

    // ---- single pass: scores -> p = exp(e - m_ub) -> mma, fragment-resident ----
    int w = t >> 5, lane = t & 31;
    int q = lane >> 2, cpos = (lane & 3) * 2;
    int j0 = w * 16 + q;
    int j1 = j0 + 8;

    const float* efT = g_efm + h * (Vn * Vn);
    float dst0 = sDst[j0], dst1 = sDst[j1];
    float maxSrcV = sMax[0];
    float efg = decf(g_efgmax_u[h]);  // per-head global upper bound on efm
    float m0v = lrelu(maxSrcV + dst0 + efg);
    float m1v = lrelu(maxSrcV + dst1 + efg);

    int rowoffBt = ((lane >> 3) & 1) * 8 + (lane & 7);
    int coloffBt = (lane >> 4) * 8;
    uint32_t aWh = sptr(sWh), aWl = sptr(sWl);

    float acc[8][4];
#pragma unroll
    for (int nt = 0; nt < 8; nt++)
#pragma unroll
        for (int r = 0; r < 4; r++) acc[nt][r] = 0.f;

    float s0 = 0.f, s1 = 0.f;
#pragma unroll
    for (int k0 = 0; k0 < 8; k0++) {
        int ib = k0 * 16 + cpos;
        float2 sA = *(const float2*)&sSrc[ib];
        float2 sB = *(const float2*)&sSrc[ib + 8];
        float2 eA0 = *(const float2*)&efT[j0 * Vn + ib];
        float2 eB0 = *(const float2*)&efT[j0 * Vn + ib + 8];
        float2 eA1 = *(const float2*)&efT[j1 * Vn + ib];
        float2 eB1 = *(const float2*)&efT[j1 * Vn + ib + 8];
        float p00 = __expf(lrelu(sA.x + dst0 + eA0.x) - m0v);
        float p01 = __expf(lrelu(sA.y + dst0 + eA0.y) - m0v);
        float p02 = __expf(lrelu(sB.x + dst0 + eB0.x) - m0v);
        float p03 = __expf(lrelu(sB.y + dst0 + eB0.y) - m0v);
        float p10 = __expf(lrelu(sA.x + dst1 + eA1.x) - m1v);
        float p11 = __expf(lrelu(sA.y + dst1 + eA1.y) - m1v);
        float p12 = __expf(lrelu(sB.x + dst1 + eB1.x) - m1v);
        float p13 = __expf(lrelu(sB.y + dst1 + eB1.y) - m1v);
        s0 += p00 + p01 + p02 + p03;
        s1 += p10 + p11 + p12 + p13;
        uint32_t Ah[4], Al[4];
        split2(p00, p01, Ah[0], Al[0]);
        split2(p10, p11, Ah[1], Al[1]);
        split2(p02, p03, Ah[2], Al[2]);
        split2(p12, p13, Ah[3], Al[3]);
#pragma unroll
        for (int nc = 0; nc < 4; nc++) {
            uint32_t offB = ((k0 * 16 + rowoffBt) * WSTR + nc * 16 + coloffBt) * 2;
            uint32_t bh0, bh1, bh2, bh3, bl0, bl1, bl2, bl3;
            ldsm_x4_t(bh0, bh1, bh2, bh3, aWh + offB);
            ldsm_x4_t(bl0, bl1, bl2, bl3, aWl + offB);
            mma_bf16(acc[nc * 2], Ah, bh0, bh1);
            mma_bf16(acc[nc * 2], Al, bh0, bh1);
            mma_bf16(acc[nc * 2], Ah, bl0, bl1);
            mma_bf16(acc[nc * 2 + 1], Ah, bh2, bh3);
            mma_bf16(acc[nc * 2 + 1], Al, bh2, bh3);
            mma_bf16(acc[nc * 2 + 1], Ah, bl2, bl3);
        }
    }
    s0 += __shfl_xor_sync(0xffffffffu, s0, 1);
    s0 += __shfl_xor_sync(0xffffffffu, s0, 2);
    s1 += __shfl_xor_sync(0xffffffffu, s1, 1);
    s1 += __shfl_xor_sync(0xffffffffu, s1, 2);
    float inv0 = 1.0f / s0;
    float inv1 = 1.0f / s1;

    bool msk0 = (sMb[j0] != 0.f);
    bool msk1 = (sMb[j1] != 0.f);
#pragma unroll
    for (int nt = 0; nt < 8; nt++) {
        int dd = nt * 8 + cpos;
        {
            float v0 = acc[nt][0] * inv0;
            float v1 = acc[nt][1] * inv0;
            float2 o;
            o.x = msk0 ? 0.f : (v0 > 0.f ? v0 : __expf(v0) - 1.f);
            o.y = msk0 ? 0.f : (v1 > 0.f ? v1 : __expf(v1) - 1.f);
            *(float2*)(out + (size_t)(b * Vn + j0) * Dn + h * DHn + dd) = o;
        }
        {
            float v0 = acc[nt][2] * inv1;
            float v1 = acc[nt][3] * inv1;
            float2 o;
            o.x = msk1 ? 0.f : (v0 > 0.f ? v0 : __expf(v0) - 1.f);
            o.y = msk1 ? 0.f : (v1 > 0.f ? v1 : __expf(v1) - 1.f);
            *(float2*)(out + (size_t)(b * Vn + j1) * Dn + h * DHn + dd) = o;
        }
    }
}

// ---------------- launch ----------------
extern "C" void kernel_launch(void* const* d_in, const int* in_sizes, int n_in,
                              void* d_out, int out_size) {
    const float* x    = (const float*)d_in[0];
    const int*   adj  = (const int*)d_in[1];
    const float* ea   = (const float*)d_in[2];
    const void*  mask = (const void*)d_in[3];
    const float* W    = (const float*)d_in[4];
    const float* a    = (const float*)d_in[5];
    const float* Ew   = (const float*)d_in[6];
    float* out = (float*)d_out;

    cudaFuncSetAttribute(gat_attn_kernel, cudaFuncAttributeMaxDynamicSharedMemorySize,
                         ATT_SMEM_BYTES);
    cudaFuncSetAttribute(gemm_wx_kernel, cudaFuncAttributeMaxDynamicSharedMemorySize,
                         GEMM_SMEM);

    prep_kernel<<<129, 256>>>(ea, Ew, adj, W, (const unsigned int*)mask);
    gemm_wx_kernel<<<(Bn * Vn) / 128, 512, GEMM_SMEM>>>(x);
    gat_attn_kernel<<<dim3(Hn, Bn), 256, ATT_SMEM_BYTES>>>(mask, a, out);
}

// round 12
// speedup vs baseline: 1.3401x; 1.0104x over previous
#include <cuda_runtime.h>
#include <cuda_bf16.h>
#include <cuda_fp16.h>
#include <math.h>
#include <stdint.h>

#define Bn 512
#define Vn 128
#define Dn 256
#define Hn 4
#define DHn 64

// ---------------- scratch (no cudaMalloc allowed) ----------------
__device__ __nv_bfloat16 g_Wh[Dn * Dn];      // W hi (bf16, gemm internal)
__device__ __nv_bfloat16 g_Wl[Dn * Dn];      // W lo
__device__ __half g_Wxh[(size_t)Bn * Vn * Dn];  // Wx hi (fp16)
__device__ __half g_Wxl[(size_t)Bn * Vn * Dn];  // Wx lo (fp16)
__device__ float g_efm[Hn * Vn * Vn];        // TRANSPOSED: [h][j][i] = adj? ef : -1e30
__device__ unsigned int g_efgmax_u[Hn];      // encoded per-head global max
__device__ int   g_mask_mode;                // 0=u8, 1=i32, 2=f32

#define NEGBIG (-1e30f)

// ---------------- helpers ----------------
__device__ __forceinline__ void mma_bf16(float* c, const uint32_t* a, uint32_t b0, uint32_t b1) {
    asm volatile(
        "mma.sync.aligned.m16n8k16.row.col.f32.bf16.bf16.f32 "
        "{%0,%1,%2,%3},{%4,%5,%6,%7},{%8,%9},{%0,%1,%2,%3};"
        : "+f"(c[0]), "+f"(c[1]), "+f"(c[2]), "+f"(c[3])
        : "r"(a[0]), "r"(a[1]), "r"(a[2]), "r"(a[3]), "r"(b0), "r"(b1));
}
__device__ __forceinline__ void mma_f16(float* c, const uint32_t* a, uint32_t b0, uint32_t b1) {
    asm volatile(
        "mma.sync.aligned.m16n8k16.row.col.f32.f16.f16.f32 "
        "{%0,%1,%2,%3},{%4,%5,%6,%7},{%8,%9},{%0,%1,%2,%3};"
        : "+f"(c[0]), "+f"(c[1]), "+f"(c[2]), "+f"(c[3])
        : "r"(a[0]), "r"(a[1]), "r"(a[2]), "r"(a[3]), "r"(b0), "r"(b1));
}

__device__ __forceinline__ void ldsm_x4(uint32_t& r0, uint32_t& r1, uint32_t& r2, uint32_t& r3,
                                        uint32_t addr) {
    asm volatile("ldmatrix.sync.aligned.m8n8.x4.shared.b16 {%0,%1,%2,%3}, [%4];"
                 : "=r"(r0), "=r"(r1), "=r"(r2), "=r"(r3) : "r"(addr));
}
__device__ __forceinline__ void ldsm_x4_t(uint32_t& r0, uint32_t& r1, uint32_t& r2, uint32_t& r3,
                                          uint32_t addr) {
    asm volatile("ldmatrix.sync.aligned.m8n8.x4.trans.shared.b16 {%0,%1,%2,%3}, [%4];"
                 : "=r"(r0), "=r"(r1), "=r"(r2), "=r"(r3) : "r"(addr));
}
__device__ __forceinline__ uint32_t sptr(const void* p) {
    return (uint32_t)__cvta_generic_to_shared(p);
}

// bf16 hi/lo split (gemm internal)
__device__ __forceinline__ void split2(float a, float b, uint32_t& hi, uint32_t& lo) {
    __nv_bfloat16 ha = __float2bfloat16_rn(a);
    __nv_bfloat16 hb = __float2bfloat16_rn(b);
    float ra = a - __bfloat162float(ha);
    float rb = b - __bfloat162float(hb);
    __nv_bfloat162 vh; vh.x = ha; vh.y = hb;
    __nv_bfloat162 vl; vl.x = __float2bfloat16_rn(ra); vl.y = __float2bfloat16_rn(rb);
    hi = *reinterpret_cast<uint32_t*>(&vh);
    lo = *reinterpret_cast<uint32_t*>(&vl);
}

// fp16 hi/lo split (Wx storage)
__device__ __forceinline__ void split2h(float a, float b, uint32_t& hi, uint32_t& lo) {
    __half2 vh = __floats2half2_rn(a, b);
    float ra = a - __half2float(vh.x);
    float rb = b - __half2float(vh.y);
    __half2 vl = __floats2half2_rn(ra, rb);
    hi = *reinterpret_cast<uint32_t*>(&vh);
    lo = *reinterpret_cast<uint32_t*>(&vl);
}

__device__ __forceinline__ float lrelu(float s) { return (s >= 0.f) ? s : 0.2f * s; }

__device__ __forceinline__ unsigned int encf(float f) {
    unsigned int u = __float_as_uint(f);
    return (u & 0x80000000u) ? ~u : (u | 0x80000000u);
}
__device__ __forceinline__ float decf(unsigned int u) {
    return (u & 0x80000000u) ? __uint_as_float(u & 0x7FFFFFFFu) : __uint_as_float(~u);
}

// ---------------- merged prep kernel ----------------
__global__ __launch_bounds__(256) void prep_kernel(const float* __restrict__ ea,
                                                   const float* __restrict__ Ew,
                                                   const int* __restrict__ adj,
                                                   const float* __restrict__ W,
                                                   const unsigned int* __restrict__ maskw) {
    int blk = blockIdx.x;
    int t = threadIdx.x;
    if (blk < 64) {
        int idx = blk * 256 + t;  // i*128 + j
        float e0 = ea[idx * 2], e1 = ea[idx * 2 + 1];
        bool ok = adj[idx] != 0;
        int i = idx >> 7, j = idx & 127;
        int tidx = j * Vn + i;
        float v0 = ok ? (e0 * Ew[0] + e1 * Ew[1]) : NEGBIG;
        float v1 = ok ? (e0 * Ew[2] + e1 * Ew[3]) : NEGBIG;
        float v2 = ok ? (e0 * Ew[4] + e1 * Ew[5]) : NEGBIG;
        float v3 = ok ? (e0 * Ew[6] + e1 * Ew[7]) : NEGBIG;
        g_efm[0 * 16384 + tidx] = v0;
        g_efm[1 * 16384 + tidx] = v1;
        g_efm[2 * 16384 + tidx] = v2;
        g_efm[3 * 16384 + tidx] = v3;
        float m[4] = {v0, v1, v2, v3};
#pragma unroll
        for (int h = 0; h < 4; h++) {
            float x = m[h];
            x = fmaxf(x, __shfl_xor_sync(0xffffffffu, x, 1));
            x = fmaxf(x, __shfl_xor_sync(0xffffffffu, x, 2));
            x = fmaxf(x, __shfl_xor_sync(0xffffffffu, x, 4));
            x = fmaxf(x, __shfl_xor_sync(0xffffffffu, x, 8));
            x = fmaxf(x, __shfl_xor_sync(0xffffffffu, x, 16));
            if ((t & 31) == 0) atomicMax(&g_efgmax_u[h], encf(x));
        }
    } else if (blk < 128) {
        int gid = (blk - 64) * 256 + t;
        float4 v = ((const float4*)W)[gid];
        uint32_t h01, l01, h23, l23;
        split2(v.x, v.y, h01, l01);
        split2(v.z, v.w, h23, l23);
        ((uint2*)g_Wh)[gid] = make_uint2(h01, h23);
        ((uint2*)g_Wl)[gid] = make_uint2(l01, l23);
    } else {
        __shared__ int okInt, okFloat;
        if (t == 0) { okInt = 1; okFloat = 1; }
        __syncthreads();
        int badI = 0, badF = 0;
        for (int idx = t; idx < 16384; idx += 256) {
            unsigned int v = maskw[idx];
            if (v > 1u) badI = 1;
            if (v != 0u && v != 0x3f800000u) badF = 1;
        }
        if (badI) okInt = 0;
        if (badF) okFloat = 0;
        __syncthreads();
        if (t == 0) g_mask_mode = okFloat ? 2 : (okInt ? 1 : 0);
    }
}

// ---------------- GEMM1: Wx = x @ W^T, BM=128 BN=256 BK=32, 512 thr ----------------
#define GSTAGE 61440
#define GEMM_SMEM (2 * GSTAGE)

__global__ __launch_bounds__(512) void gemm_wx_kernel(const float* __restrict__ x) {
    extern __shared__ char gs[];
    int m0 = blockIdx.x * 128;
    int t = threadIdx.x;
    int w = t >> 5, lane = t & 31;
    int wm = w & 3, wn = w >> 2;

    int rowoffA = ((lane >> 3) & 1) * 8 + (lane & 7);
    int coloffA = (lane >> 4) * 8;
    int rowoffB = (lane >> 4) * 8 + (lane & 7);
    int coloffB = ((lane >> 3) & 1) * 8;

    const uint4* gwh4 = (const uint4*)g_Wh;
    const uint4* gwl4 = (const uint4*)g_Wl;

    int arow0 = t >> 3, acq0 = t & 7;
    int arow1 = arow0 + 64;
    int brow0 = t >> 1, bhalf = t & 1;

    float4 ax0, ax1;
    uint4 rbh0, rbh1, rbl0, rbl1;

    float acc[2][8][4];
#pragma unroll
    for (int mt = 0; mt < 2; mt++)
#pragma unroll
        for (int nt = 0; nt < 8; nt++)
#pragma unroll
            for (int r = 0; r < 4; r++) acc[mt][nt][r] = 0.f;

#define G_LDG(k0)                                                                     \
    do {                                                                              \
        ax0 = *(const float4*)(x + (size_t)(m0 + arow0) * Dn + (k0) + acq0 * 4);      \
        ax1 = *(const float4*)(x + (size_t)(m0 + arow1) * Dn + (k0) + acq0 * 4);      \
        int bi0 = (brow0 * (Dn / 2) + ((k0) >> 1) + bhalf * 8) >> 2;                  \
        rbh0 = gwh4[bi0]; rbh1 = gwh4[bi0 + 1];                                       \
        rbl0 = gwl4[bi0]; rbl1 = gwl4[bi0 + 1];                                       \
    } while (0)

#define G_STS(s)                                                                      \
    do {                                                                              \
        char* st = gs + (s) * GSTAGE;                                                 \
        uint32_t* ah = (uint32_t*)st;                                                 \
        uint32_t* al = (uint32_t*)(st + 10240);                                       \
        uint4* bh = (uint4*)(st + 20480);                                             \
        uint4* bl = (uint4*)(st + 40960);                                             \
        uint32_t h01, l01, h23, l23;                                                  \
        split2(ax0.x, ax0.y, h01, l01); split2(ax0.z, ax0.w, h23, l23);               \
        ah[arow0 * 20 + acq0 * 2] = h01; ah[arow0 * 20 + acq0 * 2 + 1] = h23;         \
        al[arow0 * 20 + acq0 * 2] = l01; al[arow0 * 20 + acq0 * 2 + 1] = l23;         \
        split2(ax1.x, ax1.y, h01, l01); split2(ax1.z, ax1.w, h23, l23);               \
        ah[arow1 * 20 + acq0 * 2] = h01; ah[arow1 * 20 + acq0 * 2 + 1] = h23;         \
        al[arow1 * 20 + acq0 * 2] = l01; al[arow1 * 20 + acq0 * 2 + 1] = l23;         \
        bh[brow0 * 5 + bhalf * 2] = rbh0; bh[brow0 * 5 + bhalf * 2 + 1] = rbh1;       \
        bl[brow0 * 5 + bhalf * 2] = rbl0; bl[brow0 * 5 + bhalf * 2 + 1] = rbl1;       \
    } while (0)

    G_LDG(0);
    G_STS(0);
    G_LDG(32);
    __syncthreads();

    for (int ki = 0; ki < 8; ki++) {
        char* st = gs + (ki & 1) * GSTAGE;
        uint32_t aAh = sptr(st), aAl = sptr(st + 10240);
        uint32_t aBh = sptr(st + 20480), aBl = sptr(st + 40960);
#pragma unroll
        for (int ks = 0; ks < 32; ks += 16) {
            uint32_t Ah[2][4], Al[2][4];
#pragma unroll
            for (int mt = 0; mt < 2; mt++) {
                uint32_t off = (wm * 32 + mt * 16 + rowoffA) * 80 + (ks + coloffA) * 2;
                ldsm_x4(Ah[mt][0], Ah[mt][1], Ah[mt][2], Ah[mt][3], aAh + off);
                ldsm_x4(Al[mt][0], Al[mt][1], Al[mt][2], Al[mt][3], aAl + off);
            }
#pragma unroll
            for (int nb = 0; nb < 4; nb++) {
                uint32_t off = (wn * 64 + nb * 16 + rowoffB) * 80 + (ks + coloffB) * 2;
                uint32_t bh0, bh1, bh2, bh3, bl0, bl1, bl2, bl3;
                ldsm_x4(bh0, bh1, bh2, bh3, aBh + off);
                ldsm_x4(bl0, bl1, bl2, bl3, aBl + off);
#pragma unroll
                for (int mt = 0; mt < 2; mt++) {
                    mma_bf16(acc[mt][nb * 2], Ah[mt], bh0, bh1);
                    mma_bf16(acc[mt][nb * 2], Al[mt], bh0, bh1);
                    mma_bf16(acc[mt][nb * 2], Ah[mt], bl0, bl1);
                    mma_bf16(acc[mt][nb * 2 + 1], Ah[mt], bh2, bh3);
                    mma_bf16(acc[mt][nb * 2 + 1], Al[mt], bh2, bh3);
                    mma_bf16(acc[mt][nb * 2 + 1], Ah[mt], bl2, bl3);
                }
            }
        }
        __syncthreads();
        if (ki < 7) {
            G_STS((ki + 1) & 1);
            if (ki < 6) G_LDG((ki + 2) * 32);
            __syncthreads();
        }
    }

    // epilogue: write Wx as fp16 hi/lo pairs
#pragma unroll
    for (int mt = 0; mt < 2; mt++)
#pragma unroll
        for (int nt = 0; nt < 8; nt++) {
            int row0 = m0 + wm * 32 + mt * 16 + (lane >> 2);
            int col = wn * 64 + nt * 8 + (lane & 3) * 2;
            uint32_t hi, lo;
            split2h(acc[mt][nt][0], acc[mt][nt][1], hi, lo);
            *(uint32_t*)&g_Wxh[(size_t)row0 * Dn + col] = hi;
            *(uint32_t*)&g_Wxl[(size_t)row0 * Dn + col] = lo;
            split2h(acc[mt][nt][2], acc[mt][nt][3], hi, lo);
            *(uint32_t*)&g_Wxh[(size_t)(row0 + 8) * Dn + col] = hi;
            *(uint32_t*)&g_Wxl[(size_t)(row0 + 8) * Dn + col] = lo;
        }
}

// ---------------- fused attention per (b, h) ----------------
#define WSTR 72  // fp16 stride -> conflict-free ldmatrix
#define ATT_SMEM_BYTES 41088

__global__ __launch_bounds__(256, 3) void gat_attn_kernel(const void* __restrict__ maskp,
                                                          const float* __restrict__ a,
                                                          float* __restrict__ out) {
    extern __shared__ char smem[];
    __half* sWh = (__half*)smem;
    __half* sWl = (__half*)(smem + 18432);
    float* sAvec = (float*)(smem + 36864);  // 128
    float* sMb = sAvec + 128;               // 128
    float* sSrc = sAvec + 256;              // 128
    float* sDst = sAvec + 384;              // 128
    float* sPS = sAvec + 512;               // 256
    float* sPD = sAvec + 768;               // 256
    float* sMax = sAvec + 1024;             // 1

    int h = blockIdx.x;
    int b = blockIdx.y;
    int t = threadIdx.x;

    if (t < 128) {
        sAvec[t] = a[t];
        int mode = g_mask_mode;
        bool mv;
        int idx = b * Vn + t;
        if (mode == 0)      mv = ((const unsigned char*)maskp)[idx] != 0;
        else if (mode == 1) mv = ((const int*)maskp)[idx] != 0;
        else                mv = ((const float*)maskp)[idx] != 0.f;
        sMb[t] = mv ? NEGBIG : 0.f;
    }
    __syncthreads();

    // ---- load Wx[b,:,h,:] fp16 hi/lo into sW [i][d] + partial a-dots ----
    {
        int i = t >> 1, half = t & 1;
        size_t base32 = ((size_t)(b * Vn + i) * Dn + h * DHn) >> 1;
        const uint4* ph4 = (const uint4*)((const uint32_t*)g_Wxh + base32 + half * 16);
        const uint4* pl4 = (const uint4*)((const uint32_t*)g_Wxl + base32 + half * 16);
        uint4 h4[4], l4[4];
#pragma unroll
        for (int q = 0; q < 4; q++) { h4[q] = ph4[q]; l4[q] = pl4[q]; }
        uint32_t* wh32 = (uint32_t*)sWh;
        uint32_t* wl32 = (uint32_t*)sWl;
        const uint32_t* hh = (const uint32_t*)h4;
        const uint32_t* ll = (const uint32_t*)l4;
        float ss = 0.f, sd = 0.f;
#pragma unroll
        for (int q = 0; q < 16; q++) {
            uint32_t uh = hh[q], ul = ll[q];
            int d = half * 32 + q * 2;
            wh32[i * (WSTR / 2) + (d >> 1)] = uh;
            wl32[i * (WSTR / 2) + (d >> 1)] = ul;
            float2 fh = __half22float2(*(__half2*)&uh);
            float2 fl = __half22float2(*(__half2*)&ul);
            float f0 = fh.x + fl.x, f1 = fh.y + fl.y;
            ss += f0 * sAvec[d] + f1 * sAvec[d + 1];
            sd += f0 * sAvec[64 + d] + f1 * sAvec[64 + d + 1];
        }
        sPS[t] = ss;
        sPD[t] = sd;
    }
    __syncthreads();
    if (t < 128) {
        sSrc[t] = sPS[2 * t] + sPS[2 * t + 1] + sMb[t];
        sDst[t] = sPD[2 * t] + sPD[2 * t + 1] + sMb[t];
    }
    __syncthreads();
    if (t < 32) {
        float m = fmaxf(fmaxf(sSrc[t], sSrc[t + 32]), fmaxf(sSrc[t + 64], sSrc[t + 96]));
        m = fmaxf(m, __shfl_xor_sync(0xffffffffu, m, 1));
        m = fmaxf(m, __shfl_xor_sync(0xffffffffu, m, 2));
        m = fmaxf(m, __shfl_xor_sync(0xffffffffu, m, 4));
        m = fmaxf(m, __shfl_xor_sync(0xffffffffu, m, 8));
        m = fmaxf(m, __shfl_xor_sync(0xffffffffu, m, 16));
        if (t == 0) sMax[0] = m;
    }
    __syncthreads();

    // ---- single pass: scores -> p = exp(e - m_ub) fp16 -> 2x f16 mma ----
    int w = t >> 5, lane = t & 31;
    int q = lane >> 2, cpos = (lane & 3) * 2;
    int j0 = w * 16 + q;
    int j1 = j0 + 8;

    const float* efT = g_efm + h * (Vn * Vn);
    float dst0 = sDst[j0], dst1 = sDst[j1];
    float maxSrcV = sMax[0];
    float efg = decf(g_efgmax_u[h]);
    float m0v = lrelu(maxSrcV + dst0 + efg);
    float m1v = lrelu(maxSrcV + dst1 + efg);

    int rowoffBt = ((lane >> 3) & 1) * 8 + (lane & 7);
    int coloffBt = (lane >> 4) * 8;
    uint32_t aWh = sptr(sWh), aWl = sptr(sWl);

    float acc[8][4];
#pragma unroll
    for (int nt = 0; nt < 8; nt++)
#pragma unroll
        for (int r = 0; r < 4; r++) acc[nt][r] = 0.f;

    float s0 = 0.f, s1 = 0.f;
#pragma unroll
    for (int k0 = 0; k0 < 8; k0++) {
        int ib = k0 * 16 + cpos;
        float2 sA = *(const float2*)&sSrc[ib];
        float2 sB = *(const float2*)&sSrc[ib + 8];
        float2 eA0 = *(const float2*)&efT[j0 * Vn + ib];
        float2 eB0 = *(const float2*)&efT[j0 * Vn + ib + 8];
        float2 eA1 = *(const float2*)&efT[j1 * Vn + ib];
        float2 eB1 = *(const float2*)&efT[j1 * Vn + ib + 8];
        float p00 = __expf(lrelu(sA.x + dst0 + eA0.x) - m0v);
        float p01 = __expf(lrelu(sA.y + dst0 + eA0.y) - m0v);
        float p02 = __expf(lrelu(sB.x + dst0 + eB0.x) - m0v);
        float p03 = __expf(lrelu(sB.y + dst0 + eB0.y) - m0v);
        float p10 = __expf(lrelu(sA.x + dst1 + eA1.x) - m1v);
        float p11 = __expf(lrelu(sA.y + dst1 + eA1.y) - m1v);
        float p12 = __expf(lrelu(sB.x + dst1 + eB1.x) - m1v);
        float p13 = __expf(lrelu(sB.y + dst1 + eB1.y) - m1v);
        s0 += p00 + p01 + p02 + p03;
        s1 += p10 + p11 + p12 + p13;
        uint32_t A[4];
        {
            __half2 t0 = __floats2half2_rn(p00, p01);
            __half2 t1 = __floats2half2_rn(p10, p11);
            __half2 t2 = __floats2half2_rn(p02, p03);
            __half2 t3 = __floats2half2_rn(p12, p13);
            A[0] = *(uint32_t*)&t0;
            A[1] = *(uint32_t*)&t1;
            A[2] = *(uint32_t*)&t2;
            A[3] = *(uint32_t*)&t3;
        }
#pragma unroll
        for (int nc = 0; nc < 4; nc++) {
            uint32_t offB = ((k0 * 16 + rowoffBt) * WSTR + nc * 16 + coloffBt) * 2;
            uint32_t bh0, bh1, bh2, bh3, bl0, bl1, bl2, bl3;
            ldsm_x4_t(bh0, bh1, bh2, bh3, aWh + offB);
            ldsm_x4_t(bl0, bl1, bl2, bl3, aWl + offB);
            mma_f16(acc[nc * 2], A, bh0, bh1);
            mma_f16(acc[nc * 2], A, bl0, bl1);
            mma_f16(acc[nc * 2 + 1], A, bh2, bh3);
            mma_f16(acc[nc * 2 + 1], A, bl2, bl3);
        }
    }
    s0 += __shfl_xor_sync(0xffffffffu, s0, 1);
    s0 += __shfl_xor_sync(0xffffffffu, s0, 2);
    s1 += __shfl_xor_sync(0xffffffffu, s1, 1);
    s1 += __shfl_xor_sync(0xffffffffu, s1, 2);
    float inv0 = 1.0f / s0;
    float inv1 = 1.0f / s1;

    bool msk0 = (sMb[j0] != 0.f);
    bool msk1 = (sMb[j1] != 0.f);
#pragma unroll
    for (int nt = 0; nt < 8; nt++) {
        int dd = nt * 8 + cpos;
        {
            float v0 = acc[nt][0] * inv0;
            float v1 = acc[nt][1] * inv0;
            float2 o;
            o.x = msk0 ? 0.f : (v0 > 0.f ? v0 : __expf(v0) - 1.f);
            o.y = msk0 ? 0.f : (v1 > 0.f ? v1 : __expf(v1) - 1.f);
            *(float2*)(out + (size_t)(b * Vn + j0) * Dn + h * DHn + dd) = o;
        }
        {
            float v0 = acc[nt][2] * inv1;
            float v1 = acc[nt][3] * inv1;
            float2 o;
            o.x = msk1 ? 0.f : (v0 > 0.f ? v0 : __expf(v0) - 1.f);
            o.y = msk1 ? 0.f : (v1 > 0.f ? v1 : __expf(v1) - 1.f);
            *(float2*)(out + (size_t)(b * Vn + j1) * Dn + h * DHn + dd) = o;
        }
    }
}

// ---------------- launch ----------------
extern "C" void kernel_launch(void* const* d_in, const int* in_sizes, int n_in,
                              void* d_out, int out_size) {
    const float* x    = (const float*)d_in[0];
    const int*   adj  = (const int*)d_in[1];
    const float* ea   = (const float*)d_in[2];
    const void*  mask = (const void*)d_in[3];
    const float* W    = (const float*)d_in[4];
    const float* a    = (const float*)d_in[5];
    const float* Ew   = (const float*)d_in[6];
    float* out = (float*)d_out;

    cudaFuncSetAttribute(gat_attn_kernel, cudaFuncAttributeMaxDynamicSharedMemorySize,
                         ATT_SMEM_BYTES);
    cudaFuncSetAttribute(gemm_wx_kernel, cudaFuncAttributeMaxDynamicSharedMemorySize,
                         GEMM_SMEM);

    prep_kernel<<<129, 256>>>(ea, Ew, adj, W, (const unsigned int*)mask);
    gemm_wx_kernel<<<(Bn * Vn) / 128, 512, GEMM_SMEM>>>(x);
    gat_attn_kernel<<<dim3(Hn, Bn), 256, ATT_SMEM_BYTES>>>(mask, a, out);
}